// round 3
// baseline (speedup 1.0000x reference)
#include <cuda_runtime.h>
#include <math.h>
#include <stdint.h>

#define BB 128
#define LL 512
#define DD 768
#define JJ 32
#define SS 33      // J+1 segments
#define DM 200
#define DF 200
#define ROWS (BB*SS)   // 4224
#define CHUNK 32

// ---------------- scratch (no allocations allowed) ----------------
__device__ float g_pooled[ROWS * DD];   // [B*S, 768]
__device__ float g_x0[ROWS * DM];       // fc1 output
__device__ float g_qkv[ROWS * 3 * DM];  // qkv
__device__ float g_att[ROWS * DM];      // attention output (pre out-proj)
__device__ float g_y[ROWS * DM];        // pre-LN buffer
__device__ float g_x1[ROWS * DM];       // post-LN1
__device__ float g_f[ROWS * DM];        // ffn hidden
__device__ float g_x2[ROWS * DM];       // post-LN2

// =====================================================================
// Kernel 1: fused fc5 scores + per-segment softmax + weighted pooling.
// One block per (b, s). Reads hidden_state exactly once. float4 paths.
// =====================================================================
__global__ void pool_kernel(const float* __restrict__ hidden,
                            const int* __restrict__ cidx,
                            const float* __restrict__ fc5_w,
                            const float* __restrict__ fc5_b,
                            float* __restrict__ pooled) {
    extern __shared__ float sm[];
    float* s_w      = sm;                       // [768]
    float* s_rows   = sm + DD;                  // [CHUNK][768]
    float* s_scores = s_rows + CHUNK * DD;      // [CHUNK]

    int blk = blockIdx.x;
    int b = blk / SS, s = blk % SS;
    int t0 = (s == 0)  ? 0  : cidx[b * JJ + s - 1];
    int t1 = (s == JJ) ? LL : cidx[b * JJ + s];

    int tid = threadIdx.x;
    int lane = tid & 31, wid = tid >> 5;

    for (int i = tid; i < DD / 4; i += 256)
        ((float4*)s_w)[i] = ((const float4*)fc5_w)[i];
    __syncthreads();

    const int d0 = tid, d1 = tid + 256, d2 = tid + 512;
    float acc0 = 0.f, acc1 = 0.f, acc2 = 0.f;
    float m = -INFINITY, l = 0.f;

    for (int c0 = t0; c0 < t1; c0 += CHUNK) {
        int nt = min(CHUNK, t1 - c0);
        for (int tok = wid; tok < nt; tok += 8) {
            const float4* row4 = (const float4*)(hidden + ((long)b * LL + (c0 + tok)) * DD);
            float4* dst4 = (float4*)(s_rows + tok * DD);
            const float4* w4 = (const float4*)s_w;
            float pd = 0.f;
            #pragma unroll
            for (int j = 0; j < 6; j++) {
                int q = lane + 32 * j;
                float4 v = row4[q];
                dst4[q] = v;
                float4 w = w4[q];
                pd += v.x * w.x + v.y * w.y + v.z * w.z + v.w * w.w;
            }
            #pragma unroll
            for (int o = 16; o > 0; o >>= 1)
                pd += __shfl_xor_sync(0xffffffffu, pd, o);
            if (lane == 0) s_scores[tok] = pd + fc5_b[0];
        }
        __syncthreads();

        float cm = -INFINITY;
        for (int t = 0; t < nt; t++) cm = fmaxf(cm, s_scores[t]);
        float nm = fmaxf(m, cm);
        float sc = (m == -INFINITY) ? 0.f : __expf(m - nm);
        acc0 *= sc; acc1 *= sc; acc2 *= sc; l *= sc;
        for (int t = 0; t < nt; t++) {
            float p = __expf(s_scores[t] - nm);
            l += p;
            acc0 += p * s_rows[t * DD + d0];
            acc1 += p * s_rows[t * DD + d1];
            acc2 += p * s_rows[t * DD + d2];
        }
        m = nm;
        __syncthreads();
    }

    float inv = 1.f / l;
    float* out = pooled + (long)blk * DD;
    out[d0] = acc0 * inv;
    out[d1] = acc1 * inv;
    out[d2] = acc2 * inv;
}

// =====================================================================
// Tensor-core GEMM (3xTF32): C[M,N] = A[M,K] @ W[N,K]^T (+bias)(+res)(relu?)
// Block tile 128x64, 8 warps (warp grid 4m x 2n), warp tile 32x32.
// mma.sync.m16n8k8.tf32; hi/lo split for near-fp32 accuracy.
// smem: (hi,lo) float2 pairs, k-major, pitch % 16 == 4 -> conflict-free LDS.64.
// Requires M % 128 == 0 (true: M = 4224).
// =====================================================================
#define MT 128
#define NT 64
#define KT 16
#define PA 132   // float2 pitch for As2 (>=128, ==4 mod 16)
#define PB 68    // float2 pitch for Bs2 (>=64,  ==4 mod 16)

__device__ __forceinline__ float2 split_tf32(float x) {
    uint32_t hu;
    asm("cvt.rna.tf32.f32 %0, %1;" : "=r"(hu) : "f"(x));
    float hi = __uint_as_float(hu);
    uint32_t lu;
    asm("cvt.rna.tf32.f32 %0, %1;" : "=r"(lu) : "f"(x - hi));
    return make_float2(hi, __uint_as_float(lu));
}

__device__ __forceinline__ void mma_tf32(float* c,
                                         uint32_t a0, uint32_t a1, uint32_t a2, uint32_t a3,
                                         uint32_t b0, uint32_t b1) {
    asm volatile(
        "mma.sync.aligned.m16n8k8.row.col.f32.tf32.tf32.f32 "
        "{%0,%1,%2,%3}, {%4,%5,%6,%7}, {%8,%9}, {%0,%1,%2,%3};"
        : "+f"(c[0]), "+f"(c[1]), "+f"(c[2]), "+f"(c[3])
        : "r"(a0), "r"(a1), "r"(a2), "r"(a3), "r"(b0), "r"(b1));
}

__global__ void gemm_tc(const float* __restrict__ A,
                        const float* __restrict__ W,
                        const float* __restrict__ bias,
                        const float* __restrict__ res,
                        float* __restrict__ C,
                        int M, int N, int K, int relu) {
    __shared__ float2 As2[KT * PA];
    __shared__ float2 Bs2[KT * PB];

    int tid  = threadIdx.x;
    int lane = tid & 31;
    int wrp  = tid >> 5;
    int wm   = wrp & 3;        // 0..3 (m)
    int wn   = wrp >> 2;       // 0..1 (n)
    int m0   = blockIdx.x * MT;
    int n0   = blockIdx.y * NT;

    int g = lane >> 2;         // 0..7
    int t = lane & 3;          // 0..3

    float acc[2][4][4];
    #pragma unroll
    for (int mi = 0; mi < 2; mi++)
        #pragma unroll
        for (int ni = 0; ni < 4; ni++)
            #pragma unroll
            for (int r = 0; r < 4; r++) acc[mi][ni][r] = 0.f;

    // loader coords
    int lr = tid >> 2;          // 0..63
    int lk = (tid & 3) * 4;     // 0,4,8,12

    for (int k0 = 0; k0 < K; k0 += KT) {
        // ---- stage A rows lr and lr+64 ----
        #pragma unroll
        for (int h = 0; h < 2; h++) {
            int r = lr + h * 64;
            const float* p = A + (long)(m0 + r) * K + k0 + lk;
            float4 v;
            if (k0 + lk + 3 < K) v = *(const float4*)p;
            else {
                v.x = (k0 + lk + 0 < K) ? p[0] : 0.f;
                v.y = (k0 + lk + 1 < K) ? p[1] : 0.f;
                v.z = (k0 + lk + 2 < K) ? p[2] : 0.f;
                v.w = (k0 + lk + 3 < K) ? p[3] : 0.f;
            }
            As2[(lk + 0) * PA + r] = split_tf32(v.x);
            As2[(lk + 1) * PA + r] = split_tf32(v.y);
            As2[(lk + 2) * PA + r] = split_tf32(v.z);
            As2[(lk + 3) * PA + r] = split_tf32(v.w);
        }
        // ---- stage W row lr (n index) ----
        {
            int n = lr;
            int gn = n0 + n;
            float4 v = make_float4(0.f, 0.f, 0.f, 0.f);
            if (gn < N) {
                const float* p = W + (long)gn * K + k0 + lk;
                if (k0 + lk + 3 < K) v = *(const float4*)p;
                else {
                    if (k0 + lk + 0 < K) v.x = p[0];
                    if (k0 + lk + 1 < K) v.y = p[1];
                    if (k0 + lk + 2 < K) v.z = p[2];
                    if (k0 + lk + 3 < K) v.w = p[3];
                }
            }
            Bs2[(lk + 0) * PB + n] = split_tf32(v.x);
            Bs2[(lk + 1) * PB + n] = split_tf32(v.y);
            Bs2[(lk + 2) * PB + n] = split_tf32(v.z);
            Bs2[(lk + 3) * PB + n] = split_tf32(v.w);
        }
        __syncthreads();

        #pragma unroll
        for (int ks = 0; ks < KT; ks += 8) {
            // A fragments: 2 m-tiles
            float2 af[2][4];
            #pragma unroll
            for (int mi = 0; mi < 2; mi++) {
                int mb = wm * 32 + mi * 16;
                af[mi][0] = As2[(ks + t) * PA + mb + g];
                af[mi][1] = As2[(ks + t) * PA + mb + g + 8];
                af[mi][2] = As2[(ks + 4 + t) * PA + mb + g];
                af[mi][3] = As2[(ks + 4 + t) * PA + mb + g + 8];
            }
            // B fragments: 4 n-tiles
            float2 bf[4][2];
            #pragma unroll
            for (int ni = 0; ni < 4; ni++) {
                int nb = wn * 32 + ni * 8;
                bf[ni][0] = Bs2[(ks + t) * PB + nb + g];
                bf[ni][1] = Bs2[(ks + 4 + t) * PB + nb + g];
            }
            #pragma unroll
            for (int mi = 0; mi < 2; mi++) {
                uint32_t ah0 = __float_as_uint(af[mi][0].x);
                uint32_t ah1 = __float_as_uint(af[mi][1].x);
                uint32_t ah2 = __float_as_uint(af[mi][2].x);
                uint32_t ah3 = __float_as_uint(af[mi][3].x);
                uint32_t al0 = __float_as_uint(af[mi][0].y);
                uint32_t al1 = __float_as_uint(af[mi][1].y);
                uint32_t al2 = __float_as_uint(af[mi][2].y);
                uint32_t al3 = __float_as_uint(af[mi][3].y);
                #pragma unroll
                for (int ni = 0; ni < 4; ni++) {
                    uint32_t bh0 = __float_as_uint(bf[ni][0].x);
                    uint32_t bh1 = __float_as_uint(bf[ni][1].x);
                    uint32_t bl0 = __float_as_uint(bf[ni][0].y);
                    uint32_t bl1 = __float_as_uint(bf[ni][1].y);
                    float* c = acc[mi][ni];
                    mma_tf32(c, ah0, ah1, ah2, ah3, bh0, bh1);  // hi*hi
                    mma_tf32(c, ah0, ah1, ah2, ah3, bl0, bl1);  // hi*lo
                    mma_tf32(c, al0, al1, al2, al3, bh0, bh1);  // lo*hi
                }
            }
        }
        __syncthreads();
    }

    // ---- epilogue ----
    #pragma unroll
    for (int mi = 0; mi < 2; mi++) {
        int row0 = m0 + wm * 32 + mi * 16 + g;
        int row1 = row0 + 8;
        #pragma unroll
        for (int ni = 0; ni < 4; ni++) {
            int col = n0 + wn * 32 + ni * 8 + 2 * t;
            if (col >= N) continue;           // col even, N even -> col+1 < N
            float* c = acc[mi][ni];
            float2 bv = make_float2(0.f, 0.f);
            if (bias) bv = *(const float2*)(bias + col);
            float2 v0 = make_float2(c[0] + bv.x, c[1] + bv.y);
            float2 v1 = make_float2(c[2] + bv.x, c[3] + bv.y);
            if (res) {
                float2 r0 = *(const float2*)(res + (long)row0 * N + col);
                float2 r1 = *(const float2*)(res + (long)row1 * N + col);
                v0.x += r0.x; v0.y += r0.y;
                v1.x += r1.x; v1.y += r1.y;
            }
            if (relu) {
                v0.x = fmaxf(v0.x, 0.f); v0.y = fmaxf(v0.y, 0.f);
                v1.x = fmaxf(v1.x, 0.f); v1.y = fmaxf(v1.y, 0.f);
            }
            *(float2*)(C + (long)row0 * N + col) = v0;
            *(float2*)(C + (long)row1 * N + col) = v1;
        }
    }
}

// =====================================================================
// Single-head attention, S=33, DM=200. Grid (B, 2): i-rows split per block.
// =====================================================================
#define PP 34   // score row pitch
#define IH 17   // max rows per block
__global__ void attn_kernel(const float* __restrict__ qkv,
                            float* __restrict__ att) {
    extern __shared__ float sm[];
    float* sq = sm;                 // [IH][200]
    float* sk = sq + IH * DM;       // [33][200]
    float* sv = sk + SS * DM;       // [33][200]
    float* sp = sv + SS * DM;       // [IH][34]

    int b = blockIdx.x, half = blockIdx.y, tid = threadIdx.x;
    int lane = tid & 31, wid = tid >> 5;
    int i0 = half * IH;
    int ih = (half == 0) ? IH : (SS - IH);   // 17 or 16

    const float* base = qkv + (long)b * SS * 3 * DM;
    // load Q rows [i0, i0+ih)
    for (int i = tid; i < ih * (DM / 4); i += 256) {
        int s = i / (DM / 4), c4 = i % (DM / 4);
        *(float4*)(sq + s * DM + c4 * 4) =
            *(const float4*)(base + (long)(i0 + s) * 3 * DM + c4 * 4);
    }
    // load K, V all rows
    for (int i = tid; i < SS * (DM / 4); i += 256) {
        int s = i / (DM / 4), c4 = i % (DM / 4);
        *(float4*)(sk + s * DM + c4 * 4) =
            *(const float4*)(base + (long)s * 3 * DM + DM + c4 * 4);
        *(float4*)(sv + s * DM + c4 * 4) =
            *(const float4*)(base + (long)s * 3 * DM + 2 * DM + c4 * 4);
    }
    __syncthreads();

    // scores: tasks = (local i, j-tile of 4): ih * 9
    const float scale = 0.0707106781186547524f; // 1/sqrt(200)
    for (int idx = tid; idx < ih * 9; idx += 256) {
        int i = idx / 9, jt = idx % 9;
        int j0 = jt * 4;
        float a0 = 0.f, a1 = 0.f, a2 = 0.f, a3 = 0.f;
        const float4* q4  = (const float4*)(sq + i * DM);
        const float4* k0p = (const float4*)(sk + (j0 + 0) * DM);
        const float4* k1p = (const float4*)(sk + (j0 + 1 < SS ? j0 + 1 : j0) * DM);
        const float4* k2p = (const float4*)(sk + (j0 + 2 < SS ? j0 + 2 : j0) * DM);
        const float4* k3p = (const float4*)(sk + (j0 + 3 < SS ? j0 + 3 : j0) * DM);
        #pragma unroll 5
        for (int c = 0; c < DM / 4; c++) {
            float4 q = q4[c];
            float4 k0v = k0p[c], k1v = k1p[c], k2v = k2p[c], k3v = k3p[c];
            a0 += q.x * k0v.x + q.y * k0v.y + q.z * k0v.z + q.w * k0v.w;
            a1 += q.x * k1v.x + q.y * k1v.y + q.z * k1v.z + q.w * k1v.w;
            a2 += q.x * k2v.x + q.y * k2v.y + q.z * k2v.z + q.w * k2v.w;
            a3 += q.x * k3v.x + q.y * k3v.y + q.z * k3v.z + q.w * k3v.w;
        }
        sp[i * PP + j0] = a0 * scale;
        if (j0 + 1 < SS) sp[i * PP + j0 + 1] = a1 * scale;
        if (j0 + 2 < SS) sp[i * PP + j0 + 2] = a2 * scale;
        if (j0 + 3 < SS) sp[i * PP + j0 + 3] = a3 * scale;
    }
    __syncthreads();

    // softmax: one warp per local row
    for (int i = wid; i < ih; i += 8) {
        float* row = sp + i * PP;
        float v0 = (lane < SS) ? row[lane] : -INFINITY;
        float v1 = (lane + 32 < SS) ? row[lane + 32] : -INFINITY;
        float mx = fmaxf(v0, v1);
        #pragma unroll
        for (int o = 16; o > 0; o >>= 1)
            mx = fmaxf(mx, __shfl_xor_sync(0xffffffffu, mx, o));
        float e0 = (lane < SS) ? __expf(v0 - mx) : 0.f;
        float e1 = (lane + 32 < SS) ? __expf(v1 - mx) : 0.f;
        float sum = e0 + e1;
        #pragma unroll
        for (int o = 16; o > 0; o >>= 1)
            sum += __shfl_xor_sync(0xffffffffu, sum, o);
        float inv = 1.f / sum;
        if (lane < SS) row[lane] = e0 * inv;
        if (lane + 32 < SS) row[lane + 32] = e1 * inv;
    }
    __syncthreads();

    // PV: outputs (local i, c4): ih * 50
    for (int idx = tid; idx < ih * (DM / 4); idx += 256) {
        int i = idx / (DM / 4), c4 = idx % (DM / 4);
        float4 acc = make_float4(0.f, 0.f, 0.f, 0.f);
        const float* prow = sp + i * PP;
        #pragma unroll 3
        for (int j = 0; j < SS; j++) {
            float p = prow[j];
            float4 v = *(const float4*)(sv + j * DM + c4 * 4);
            acc.x += p * v.x; acc.y += p * v.y; acc.z += p * v.z; acc.w += p * v.w;
        }
        *(float4*)(att + ((long)b * SS + i0 + i) * DM + c4 * 4) = acc;
    }
}

// =====================================================================
// LayerNorm over DM=200, one warp per row
// =====================================================================
__global__ void ln_kernel(const float* __restrict__ x,
                          const float* __restrict__ g,
                          const float* __restrict__ bta,
                          float* __restrict__ y, int M) {
    int row = blockIdx.x * 8 + (threadIdx.x >> 5);
    int lane = threadIdx.x & 31;
    if (row >= M) return;
    const float* xr = x + (long)row * DM;
    float vals[7];
    float s = 0.f;
    #pragma unroll
    for (int i = 0; i < 7; i++) {
        int d = lane + 32 * i;
        vals[i] = (d < DM) ? xr[d] : 0.f;
        s += vals[i];
    }
    #pragma unroll
    for (int o = 16; o > 0; o >>= 1) s += __shfl_xor_sync(0xffffffffu, s, o);
    float mean = s / (float)DM;
    float vs = 0.f;
    #pragma unroll
    for (int i = 0; i < 7; i++) {
        int d = lane + 32 * i;
        if (d < DM) { float tt = vals[i] - mean; vs += tt * tt; }
    }
    #pragma unroll
    for (int o = 16; o > 0; o >>= 1) vs += __shfl_xor_sync(0xffffffffu, vs, o);
    float inv = rsqrtf(vs / (float)DM + 1e-5f);
    float* yr = y + (long)row * DM;
    #pragma unroll
    for (int i = 0; i < 7; i++) {
        int d = lane + 32 * i;
        if (d < DM) yr[d] = (vals[i] - mean) * inv * g[d] + bta[d];
    }
}

// =====================================================================
// Final head: warp-per-output with shuffle reduction
// =====================================================================
__global__ void head_kernel(const float* __restrict__ x,
                            const float* __restrict__ fcw,
                            const float* __restrict__ fcb,
                            float* __restrict__ out) {
    int b = blockIdx.x;
    int lane = threadIdx.x & 31, wid = threadIdx.x >> 5;
    const float* x0 = x + (long)b * SS * DM;
    for (int oid = wid; oid < (SS - 1) * 2; oid += 8) {
        int srow = 1 + (oid >> 1), c = oid & 1;
        const float* xs = x0 + (long)srow * DM;
        const float* w  = fcw + c * (2 * DM);
        float d = 0.f;
        #pragma unroll
        for (int i = 0; i < 7; i++) {
            int k = lane + 32 * i;
            if (k < DM) d += w[k] * x0[k] + w[DM + k] * xs[k];
        }
        #pragma unroll
        for (int o = 16; o > 0; o >>= 1)
            d += __shfl_xor_sync(0xffffffffu, d, o);
        if (lane == 0)
            out[((long)b * (SS - 1) + (srow - 1)) * 2 + c] = d + fcb[c];
    }
}

// =====================================================================
// Launch
// =====================================================================
extern "C" void kernel_launch(void* const* d_in, const int* in_sizes, int n_in,
                              void* d_out, int out_size) {
    const float* hidden     = (const float*)d_in[0];
    const int*   cidx       = (const int*)  d_in[1];
    const float* fc5_w      = (const float*)d_in[2];
    const float* fc5_b      = (const float*)d_in[3];
    const float* fc1_w      = (const float*)d_in[4];
    const float* fc1_b      = (const float*)d_in[5];
    const float* attn_in_w  = (const float*)d_in[6];
    const float* attn_in_b  = (const float*)d_in[7];
    const float* attn_out_w = (const float*)d_in[8];
    const float* attn_out_b = (const float*)d_in[9];
    const float* ln1_g      = (const float*)d_in[10];
    const float* ln1_b      = (const float*)d_in[11];
    const float* lin1_w     = (const float*)d_in[12];
    const float* lin1_b     = (const float*)d_in[13];
    const float* lin2_w     = (const float*)d_in[14];
    const float* lin2_b     = (const float*)d_in[15];
    const float* ln2_g      = (const float*)d_in[16];
    const float* ln2_b      = (const float*)d_in[17];
    const float* fc_w       = (const float*)d_in[18];
    const float* fc_b       = (const float*)d_in[19];
    float* out = (float*)d_out;

    float *pooled, *x0, *qkv, *att, *y, *x1, *f, *x2;
    cudaGetSymbolAddress((void**)&pooled, g_pooled);
    cudaGetSymbolAddress((void**)&x0,  g_x0);
    cudaGetSymbolAddress((void**)&qkv, g_qkv);
    cudaGetSymbolAddress((void**)&att, g_att);
    cudaGetSymbolAddress((void**)&y,   g_y);
    cudaGetSymbolAddress((void**)&x1,  g_x1);
    cudaGetSymbolAddress((void**)&f,   g_f);
    cudaGetSymbolAddress((void**)&x2,  g_x2);

    const int pool_smem = (DD + CHUNK * DD + CHUNK) * (int)sizeof(float);          // ~101.5 KB
    const int attn_smem = ((IH + 2 * SS) * DM + IH * PP) * (int)sizeof(float);     // ~68.7 KB
    cudaFuncSetAttribute(pool_kernel, cudaFuncAttributeMaxDynamicSharedMemorySize, pool_smem);
    cudaFuncSetAttribute(attn_kernel, cudaFuncAttributeMaxDynamicSharedMemorySize, attn_smem);

    // 1. fused scores + segment softmax + pooling (single pass over 201 MB)
    pool_kernel<<<BB * SS, 256, pool_smem>>>(hidden, cidx, fc5_w, fc5_b, pooled);

    // 2. fc1: [4224,768] @ [768,200]^T  (tensor core, 3xTF32)
    gemm_tc<<<dim3(33, 4), 256>>>(pooled, fc1_w, fc1_b, nullptr, x0, ROWS, DM, DD, 0);

    // 3. qkv: [4224,200] @ [200,600]^T
    gemm_tc<<<dim3(33, 10), 256>>>(x0, attn_in_w, attn_in_b, nullptr, qkv, ROWS, 3 * DM, DM, 0);

    // 4. single-head attention, 2 blocks per batch
    attn_kernel<<<dim3(BB, 2), 256, attn_smem>>>(qkv, att);

    // 5. out-proj + residual -> LN1
    gemm_tc<<<dim3(33, 4), 256>>>(att, attn_out_w, attn_out_b, x0, y, ROWS, DM, DM, 0);
    ln_kernel<<<(ROWS + 7) / 8, 256>>>(y, ln1_g, ln1_b, x1, ROWS);

    // 6. FFN: relu(x@lin1^T) @ lin2^T + residual -> LN2
    gemm_tc<<<dim3(33, 4), 256>>>(x1, lin1_w, lin1_b, nullptr, f, ROWS, DM, DM, 1);
    gemm_tc<<<dim3(33, 4), 256>>>(f, lin2_w, lin2_b, x1, y, ROWS, DM, DM, 0);
    ln_kernel<<<(ROWS + 7) / 8, 256>>>(y, ln2_g, ln2_b, x2, ROWS);

    // 7. classifier head
    head_kernel<<<BB, 256>>>(x2, fc_w, fc_b, out);
}

// round 4
// speedup vs baseline: 1.4097x; 1.4097x over previous
#include <cuda_runtime.h>
#include <math.h>
#include <stdint.h>

#define BB 128
#define LL 512
#define DD 768
#define JJ 32
#define SS 33      // J+1 segments
#define DM 200
#define DF 200
#define ROWS (BB*SS)   // 4224
#define CHUNK 32

// ---------------- scratch (no allocations allowed) ----------------
__device__ float g_pooled[ROWS * DD];   // [B*S, 768]
__device__ float g_x0[ROWS * DM];       // fc1 output
__device__ float g_qkv[ROWS * 3 * DM];  // qkv
__device__ float g_att[ROWS * DM];      // attention output (pre out-proj)
__device__ float g_y[ROWS * DM];        // pre-LN buffer
__device__ float g_x1[ROWS * DM];       // post-LN1
__device__ float g_f[ROWS * DM];        // ffn hidden
__device__ float g_x2[ROWS * DM];       // post-LN2

// =====================================================================
// Kernel 1: fused fc5 scores + per-segment softmax + weighted pooling.
// One block per (b, s). Reads hidden_state exactly once. float4 paths.
// =====================================================================
__global__ void pool_kernel(const float* __restrict__ hidden,
                            const int* __restrict__ cidx,
                            const float* __restrict__ fc5_w,
                            const float* __restrict__ fc5_b,
                            float* __restrict__ pooled) {
    extern __shared__ float sm[];
    float* s_w      = sm;                       // [768]
    float* s_rows   = sm + DD;                  // [CHUNK][768]
    float* s_scores = s_rows + CHUNK * DD;      // [CHUNK]

    int blk = blockIdx.x;
    int b = blk / SS, s = blk % SS;
    int t0 = (s == 0)  ? 0  : cidx[b * JJ + s - 1];
    int t1 = (s == JJ) ? LL : cidx[b * JJ + s];

    int tid = threadIdx.x;
    int lane = tid & 31, wid = tid >> 5;

    for (int i = tid; i < DD / 4; i += 256)
        ((float4*)s_w)[i] = ((const float4*)fc5_w)[i];
    __syncthreads();

    const int d0 = tid, d1 = tid + 256, d2 = tid + 512;
    float acc0 = 0.f, acc1 = 0.f, acc2 = 0.f;
    float m = -INFINITY, l = 0.f;

    for (int c0 = t0; c0 < t1; c0 += CHUNK) {
        int nt = min(CHUNK, t1 - c0);
        for (int tok = wid; tok < nt; tok += 8) {
            const float4* row4 = (const float4*)(hidden + ((long)b * LL + (c0 + tok)) * DD);
            float4* dst4 = (float4*)(s_rows + tok * DD);
            const float4* w4 = (const float4*)s_w;
            float pd = 0.f;
            #pragma unroll
            for (int j = 0; j < 6; j++) {
                int q = lane + 32 * j;
                float4 v = row4[q];
                dst4[q] = v;
                float4 w = w4[q];
                pd += v.x * w.x + v.y * w.y + v.z * w.z + v.w * w.w;
            }
            #pragma unroll
            for (int o = 16; o > 0; o >>= 1)
                pd += __shfl_xor_sync(0xffffffffu, pd, o);
            if (lane == 0) s_scores[tok] = pd + fc5_b[0];
        }
        __syncthreads();

        float cm = -INFINITY;
        for (int t = 0; t < nt; t++) cm = fmaxf(cm, s_scores[t]);
        float nm = fmaxf(m, cm);
        float sc = (m == -INFINITY) ? 0.f : __expf(m - nm);
        acc0 *= sc; acc1 *= sc; acc2 *= sc; l *= sc;
        for (int t = 0; t < nt; t++) {
            float p = __expf(s_scores[t] - nm);
            l += p;
            acc0 += p * s_rows[t * DD + d0];
            acc1 += p * s_rows[t * DD + d1];
            acc2 += p * s_rows[t * DD + d2];
        }
        m = nm;
        __syncthreads();
    }

    float inv = 1.f / l;
    float* out = pooled + (long)blk * DD;
    out[d0] = acc0 * inv;
    out[d1] = acc1 * inv;
    out[d2] = acc2 * inv;
}

// =====================================================================
// Tensor-core GEMM (3xTF32), v2: cp.async double-buffered pipeline.
// C[M,N] = A[M,K] @ W[N,K]^T (+bias)(+res)(relu?)
// Block tile 128x64, 8 warps (4m x 2n), warp tile 32x32, k-step 16.
// smem holds RAW fp32 ([row][k], pitch 20 -> conflict-free LDS.32);
// tf32 hi/lo split happens on fragment load (registers only).
// Requires M % 128 == 0 (true: M = 4224).
// =====================================================================
#define KT 16
#define PAF 20                    // row pitch in floats (16 + 4 pad; 20*g mod 32 spreads banks)
#define A_BUF (128 * PAF)         // 2560 floats
#define B_BUF (64 * PAF)          // 1280 floats

__device__ __forceinline__ void cp_async16(float* smem_dst, const float* gsrc, int src_bytes) {
    uint32_t s = (uint32_t)__cvta_generic_to_shared(smem_dst);
    asm volatile("cp.async.cg.shared.global [%0], [%1], 16, %2;"
                 :: "r"(s), "l"(gsrc), "r"(src_bytes));
}
__device__ __forceinline__ void cp_commit() {
    asm volatile("cp.async.commit_group;");
}
template <int N>
__device__ __forceinline__ void cp_wait() {
    asm volatile("cp.async.wait_group %0;" :: "n"(N));
}

__device__ __forceinline__ float2 split_tf32(float x) {
    uint32_t hu;
    asm("cvt.rna.tf32.f32 %0, %1;" : "=r"(hu) : "f"(x));
    float hi = __uint_as_float(hu);
    uint32_t lu;
    asm("cvt.rna.tf32.f32 %0, %1;" : "=r"(lu) : "f"(x - hi));
    return make_float2(hi, __uint_as_float(lu));
}

__device__ __forceinline__ void mma_tf32(float* c,
                                         uint32_t a0, uint32_t a1, uint32_t a2, uint32_t a3,
                                         uint32_t b0, uint32_t b1) {
    asm volatile(
        "mma.sync.aligned.m16n8k8.row.col.f32.tf32.tf32.f32 "
        "{%0,%1,%2,%3}, {%4,%5,%6,%7}, {%8,%9}, {%0,%1,%2,%3};"
        : "+f"(c[0]), "+f"(c[1]), "+f"(c[2]), "+f"(c[3])
        : "r"(a0), "r"(a1), "r"(a2), "r"(a3), "r"(b0), "r"(b1));
}

__global__ __launch_bounds__(256) void gemm_tc(
        const float* __restrict__ A,
        const float* __restrict__ W,
        const float* __restrict__ bias,
        const float* __restrict__ res,
        float* __restrict__ C,
        int M, int N, int K, int relu) {
    __shared__ float As[2 * A_BUF];
    __shared__ float Bs[2 * B_BUF];

    int tid  = threadIdx.x;
    int lane = tid & 31;
    int wrp  = tid >> 5;
    int wm   = wrp & 3;        // 0..3 (m)
    int wn   = wrp >> 2;       // 0..1 (n)
    int m0   = blockIdx.x * 128;
    int n0   = blockIdx.y * 64;

    int g = lane >> 2;         // 0..7
    int t = lane & 3;          // 0..3

    float acc[2][4][4];
    #pragma unroll
    for (int mi = 0; mi < 2; mi++)
        #pragma unroll
        for (int ni = 0; ni < 4; ni++)
            #pragma unroll
            for (int r = 0; r < 4; r++) acc[mi][ni][r] = 0.f;

    // loader coords: thread -> (row = tid>>2 [+64], k4 = (tid&3)*4)
    int lr = tid >> 2;          // 0..63
    int lk = (tid & 3) * 4;     // 0,4,8,12

    int NK = (K + KT - 1) / KT;

    // ---- stage one k-tile into buffer (buf) ----
    auto stage = [&](int kt, int buf) {
        int k0 = kt * KT;
        int kb = (K - (k0 + lk)) * 4;              // valid bytes at this offset
        int sb = kb < 0 ? 0 : (kb > 16 ? 16 : kb);
        int ko = k0 + lk;
        if (ko > K - 4) ko = (K - 4 < 0) ? 0 : K - 4;  // keep src in-bounds
        float* abuf = As + buf * A_BUF;
        float* bbuf = Bs + buf * B_BUF;
        // A rows lr and lr+64 (always valid: M % 128 == 0)
        cp_async16(abuf + lr * PAF + lk,        A + (long)(m0 + lr) * K + ko,      sb);
        cp_async16(abuf + (lr + 64) * PAF + lk, A + (long)(m0 + lr + 64) * K + ko, sb);
        // W row lr (n index), guard N
        int gn = n0 + lr;
        int wb = (gn < N) ? sb : 0;
        int gnc = (gn < N) ? gn : N - 1;
        cp_async16(bbuf + lr * PAF + lk, W + (long)gnc * K + ko, wb);
    };

    stage(0, 0);
    cp_commit();

    for (int kt = 0; kt < NK; kt++) {
        if (kt + 1 < NK) {
            stage(kt + 1, (kt + 1) & 1);
            cp_commit();
            cp_wait<1>();
        } else {
            cp_wait<0>();
        }
        __syncthreads();

        const float* abuf = As + (kt & 1) * A_BUF;
        const float* bbuf = Bs + (kt & 1) * B_BUF;

        #pragma unroll
        for (int ks = 0; ks < KT; ks += 8) {
            // A fragments raw -> split
            float2 ah[2][4];  // {hi in .x, lo in .y}
            #pragma unroll
            for (int mi = 0; mi < 2; mi++) {
                int mb = wm * 32 + mi * 16;
                ah[mi][0] = split_tf32(abuf[(mb + g)     * PAF + ks + t]);
                ah[mi][1] = split_tf32(abuf[(mb + g + 8) * PAF + ks + t]);
                ah[mi][2] = split_tf32(abuf[(mb + g)     * PAF + ks + 4 + t]);
                ah[mi][3] = split_tf32(abuf[(mb + g + 8) * PAF + ks + 4 + t]);
            }
            // B fragments raw -> split
            float2 bh[4][2];
            #pragma unroll
            for (int ni = 0; ni < 4; ni++) {
                int nb = wn * 32 + ni * 8;
                bh[ni][0] = split_tf32(bbuf[(nb + g) * PAF + ks + t]);
                bh[ni][1] = split_tf32(bbuf[(nb + g) * PAF + ks + 4 + t]);
            }
            #pragma unroll
            for (int mi = 0; mi < 2; mi++) {
                uint32_t a0h = __float_as_uint(ah[mi][0].x);
                uint32_t a1h = __float_as_uint(ah[mi][1].x);
                uint32_t a2h = __float_as_uint(ah[mi][2].x);
                uint32_t a3h = __float_as_uint(ah[mi][3].x);
                uint32_t a0l = __float_as_uint(ah[mi][0].y);
                uint32_t a1l = __float_as_uint(ah[mi][1].y);
                uint32_t a2l = __float_as_uint(ah[mi][2].y);
                uint32_t a3l = __float_as_uint(ah[mi][3].y);
                #pragma unroll
                for (int ni = 0; ni < 4; ni++) {
                    uint32_t b0h = __float_as_uint(bh[ni][0].x);
                    uint32_t b1h = __float_as_uint(bh[ni][1].x);
                    uint32_t b0l = __float_as_uint(bh[ni][0].y);
                    uint32_t b1l = __float_as_uint(bh[ni][1].y);
                    float* c = acc[mi][ni];
                    mma_tf32(c, a0h, a1h, a2h, a3h, b0h, b1h);  // hi*hi
                    mma_tf32(c, a0h, a1h, a2h, a3h, b0l, b1l);  // hi*lo
                    mma_tf32(c, a0l, a1l, a2l, a3l, b0h, b1h);  // lo*hi
                }
            }
        }
        __syncthreads();
    }

    // ---- epilogue ----
    #pragma unroll
    for (int mi = 0; mi < 2; mi++) {
        int row0 = m0 + wm * 32 + mi * 16 + g;
        int row1 = row0 + 8;
        #pragma unroll
        for (int ni = 0; ni < 4; ni++) {
            int col = n0 + wn * 32 + ni * 8 + 2 * t;
            if (col >= N) continue;           // col even, N even -> col+1 < N
            float* c = acc[mi][ni];
            float2 bv = make_float2(0.f, 0.f);
            if (bias) bv = *(const float2*)(bias + col);
            float2 v0 = make_float2(c[0] + bv.x, c[1] + bv.y);
            float2 v1 = make_float2(c[2] + bv.x, c[3] + bv.y);
            if (res) {
                float2 r0 = *(const float2*)(res + (long)row0 * N + col);
                float2 r1 = *(const float2*)(res + (long)row1 * N + col);
                v0.x += r0.x; v0.y += r0.y;
                v1.x += r1.x; v1.y += r1.y;
            }
            if (relu) {
                v0.x = fmaxf(v0.x, 0.f); v0.y = fmaxf(v0.y, 0.f);
                v1.x = fmaxf(v1.x, 0.f); v1.y = fmaxf(v1.y, 0.f);
            }
            *(float2*)(C + (long)row0 * N + col) = v0;
            *(float2*)(C + (long)row1 * N + col) = v1;
        }
    }
}

// =====================================================================
// Single-head attention, S=33, DM=200. Grid (B, 4): i-rows split per block.
// =====================================================================
#define PP 34   // score row pitch
#define IH 9    // max rows per block (9,9,9,6)
__global__ void attn_kernel(const float* __restrict__ qkv,
                            float* __restrict__ att) {
    extern __shared__ float sm[];
    float* sq = sm;                 // [IH][200]
    float* sk = sq + IH * DM;       // [33][200]
    float* sv = sk + SS * DM;       // [33][200]
    float* sp = sv + SS * DM;       // [IH][34]

    int b = blockIdx.x, part = blockIdx.y, tid = threadIdx.x;
    int lane = tid & 31, wid = tid >> 5;
    int i0 = part * IH;
    int ih = min(IH, SS - i0);

    const float* base = qkv + (long)b * SS * 3 * DM;
    // load Q rows [i0, i0+ih)
    for (int i = tid; i < ih * (DM / 4); i += 256) {
        int s = i / (DM / 4), c4 = i % (DM / 4);
        *(float4*)(sq + s * DM + c4 * 4) =
            *(const float4*)(base + (long)(i0 + s) * 3 * DM + c4 * 4);
    }
    // load K, V all rows
    for (int i = tid; i < SS * (DM / 4); i += 256) {
        int s = i / (DM / 4), c4 = i % (DM / 4);
        *(float4*)(sk + s * DM + c4 * 4) =
            *(const float4*)(base + (long)s * 3 * DM + DM + c4 * 4);
        *(float4*)(sv + s * DM + c4 * 4) =
            *(const float4*)(base + (long)s * 3 * DM + 2 * DM + c4 * 4);
    }
    __syncthreads();

    // scores: tasks = (local i, j-tile of 4): ih * 9
    const float scale = 0.0707106781186547524f; // 1/sqrt(200)
    for (int idx = tid; idx < ih * 9; idx += 256) {
        int i = idx / 9, jt = idx % 9;
        int j0 = jt * 4;
        float a0 = 0.f, a1 = 0.f, a2 = 0.f, a3 = 0.f;
        const float4* q4  = (const float4*)(sq + i * DM);
        const float4* k0p = (const float4*)(sk + (j0 + 0) * DM);
        const float4* k1p = (const float4*)(sk + (j0 + 1 < SS ? j0 + 1 : j0) * DM);
        const float4* k2p = (const float4*)(sk + (j0 + 2 < SS ? j0 + 2 : j0) * DM);
        const float4* k3p = (const float4*)(sk + (j0 + 3 < SS ? j0 + 3 : j0) * DM);
        #pragma unroll 5
        for (int c = 0; c < DM / 4; c++) {
            float4 q = q4[c];
            float4 k0v = k0p[c], k1v = k1p[c], k2v = k2p[c], k3v = k3p[c];
            a0 += q.x * k0v.x + q.y * k0v.y + q.z * k0v.z + q.w * k0v.w;
            a1 += q.x * k1v.x + q.y * k1v.y + q.z * k1v.z + q.w * k1v.w;
            a2 += q.x * k2v.x + q.y * k2v.y + q.z * k2v.z + q.w * k2v.w;
            a3 += q.x * k3v.x + q.y * k3v.y + q.z * k3v.z + q.w * k3v.w;
        }
        sp[i * PP + j0] = a0 * scale;
        if (j0 + 1 < SS) sp[i * PP + j0 + 1] = a1 * scale;
        if (j0 + 2 < SS) sp[i * PP + j0 + 2] = a2 * scale;
        if (j0 + 3 < SS) sp[i * PP + j0 + 3] = a3 * scale;
    }
    __syncthreads();

    // softmax: one warp per local row
    for (int i = wid; i < ih; i += 8) {
        float* row = sp + i * PP;
        float v0 = (lane < SS) ? row[lane] : -INFINITY;
        float v1 = (lane + 32 < SS) ? row[lane + 32] : -INFINITY;
        float mx = fmaxf(v0, v1);
        #pragma unroll
        for (int o = 16; o > 0; o >>= 1)
            mx = fmaxf(mx, __shfl_xor_sync(0xffffffffu, mx, o));
        float e0 = (lane < SS) ? __expf(v0 - mx) : 0.f;
        float e1 = (lane + 32 < SS) ? __expf(v1 - mx) : 0.f;
        float sum = e0 + e1;
        #pragma unroll
        for (int o = 16; o > 0; o >>= 1)
            sum += __shfl_xor_sync(0xffffffffu, sum, o);
        float inv = 1.f / sum;
        if (lane < SS) row[lane] = e0 * inv;
        if (lane + 32 < SS) row[lane + 32] = e1 * inv;
    }
    __syncthreads();

    // PV: outputs (local i, c4): ih * 50
    for (int idx = tid; idx < ih * (DM / 4); idx += 256) {
        int i = idx / (DM / 4), c4 = idx % (DM / 4);
        float4 acc = make_float4(0.f, 0.f, 0.f, 0.f);
        const float* prow = sp + i * PP;
        #pragma unroll 3
        for (int j = 0; j < SS; j++) {
            float p = prow[j];
            float4 v = *(const float4*)(sv + j * DM + c4 * 4);
            acc.x += p * v.x; acc.y += p * v.y; acc.z += p * v.z; acc.w += p * v.w;
        }
        *(float4*)(att + ((long)b * SS + i0 + i) * DM + c4 * 4) = acc;
    }
}

// =====================================================================
// LayerNorm over DM=200, one warp per row
// =====================================================================
__global__ void ln_kernel(const float* __restrict__ x,
                          const float* __restrict__ g,
                          const float* __restrict__ bta,
                          float* __restrict__ y, int M) {
    int row = blockIdx.x * 8 + (threadIdx.x >> 5);
    int lane = threadIdx.x & 31;
    if (row >= M) return;
    const float* xr = x + (long)row * DM;
    float vals[7];
    float s = 0.f;
    #pragma unroll
    for (int i = 0; i < 7; i++) {
        int d = lane + 32 * i;
        vals[i] = (d < DM) ? xr[d] : 0.f;
        s += vals[i];
    }
    #pragma unroll
    for (int o = 16; o > 0; o >>= 1) s += __shfl_xor_sync(0xffffffffu, s, o);
    float mean = s / (float)DM;
    float vs = 0.f;
    #pragma unroll
    for (int i = 0; i < 7; i++) {
        int d = lane + 32 * i;
        if (d < DM) { float tt = vals[i] - mean; vs += tt * tt; }
    }
    #pragma unroll
    for (int o = 16; o > 0; o >>= 1) vs += __shfl_xor_sync(0xffffffffu, vs, o);
    float inv = rsqrtf(vs / (float)DM + 1e-5f);
    float* yr = y + (long)row * DM;
    #pragma unroll
    for (int i = 0; i < 7; i++) {
        int d = lane + 32 * i;
        if (d < DM) yr[d] = (vals[i] - mean) * inv * g[d] + bta[d];
    }
}

// =====================================================================
// Final head: warp-per-output with shuffle reduction
// =====================================================================
__global__ void head_kernel(const float* __restrict__ x,
                            const float* __restrict__ fcw,
                            const float* __restrict__ fcb,
                            float* __restrict__ out) {
    int b = blockIdx.x;
    int lane = threadIdx.x & 31, wid = threadIdx.x >> 5;
    const float* x0 = x + (long)b * SS * DM;
    for (int oid = wid; oid < (SS - 1) * 2; oid += 8) {
        int srow = 1 + (oid >> 1), c = oid & 1;
        const float* xs = x0 + (long)srow * DM;
        const float* w  = fcw + c * (2 * DM);
        float d = 0.f;
        #pragma unroll
        for (int i = 0; i < 7; i++) {
            int k = lane + 32 * i;
            if (k < DM) d += w[k] * x0[k] + w[DM + k] * xs[k];
        }
        #pragma unroll
        for (int o = 16; o > 0; o >>= 1)
            d += __shfl_xor_sync(0xffffffffu, d, o);
        if (lane == 0)
            out[((long)b * (SS - 1) + (srow - 1)) * 2 + c] = d + fcb[c];
    }
}

// =====================================================================
// Launch
// =====================================================================
extern "C" void kernel_launch(void* const* d_in, const int* in_sizes, int n_in,
                              void* d_out, int out_size) {
    const float* hidden     = (const float*)d_in[0];
    const int*   cidx       = (const int*)  d_in[1];
    const float* fc5_w      = (const float*)d_in[2];
    const float* fc5_b      = (const float*)d_in[3];
    const float* fc1_w      = (const float*)d_in[4];
    const float* fc1_b      = (const float*)d_in[5];
    const float* attn_in_w  = (const float*)d_in[6];
    const float* attn_in_b  = (const float*)d_in[7];
    const float* attn_out_w = (const float*)d_in[8];
    const float* attn_out_b = (const float*)d_in[9];
    const float* ln1_g      = (const float*)d_in[10];
    const float* ln1_b      = (const float*)d_in[11];
    const float* lin1_w     = (const float*)d_in[12];
    const float* lin1_b     = (const float*)d_in[13];
    const float* lin2_w     = (const float*)d_in[14];
    const float* lin2_b     = (const float*)d_in[15];
    const float* ln2_g      = (const float*)d_in[16];
    const float* ln2_b      = (const float*)d_in[17];
    const float* fc_w       = (const float*)d_in[18];
    const float* fc_b       = (const float*)d_in[19];
    float* out = (float*)d_out;

    float *pooled, *x0, *qkv, *att, *y, *x1, *f, *x2;
    cudaGetSymbolAddress((void**)&pooled, g_pooled);
    cudaGetSymbolAddress((void**)&x0,  g_x0);
    cudaGetSymbolAddress((void**)&qkv, g_qkv);
    cudaGetSymbolAddress((void**)&att, g_att);
    cudaGetSymbolAddress((void**)&y,   g_y);
    cudaGetSymbolAddress((void**)&x1,  g_x1);
    cudaGetSymbolAddress((void**)&f,   g_f);
    cudaGetSymbolAddress((void**)&x2,  g_x2);

    const int pool_smem = (DD + CHUNK * DD + CHUNK) * (int)sizeof(float);          // ~101.5 KB
    const int attn_smem = ((IH + 2 * SS) * DM + IH * PP) * (int)sizeof(float);     // ~61.2 KB
    cudaFuncSetAttribute(pool_kernel, cudaFuncAttributeMaxDynamicSharedMemorySize, pool_smem);
    cudaFuncSetAttribute(attn_kernel, cudaFuncAttributeMaxDynamicSharedMemorySize, attn_smem);

    // 1. fused scores + segment softmax + pooling (single pass over 201 MB)
    pool_kernel<<<BB * SS, 256, pool_smem>>>(hidden, cidx, fc5_w, fc5_b, pooled);

    // 2. fc1: [4224,768] @ [768,200]^T  (tensor core, 3xTF32, pipelined)
    gemm_tc<<<dim3(33, 4), 256>>>(pooled, fc1_w, fc1_b, nullptr, x0, ROWS, DM, DD, 0);

    // 3. qkv: [4224,200] @ [200,600]^T
    gemm_tc<<<dim3(33, 10), 256>>>(x0, attn_in_w, attn_in_b, nullptr, qkv, ROWS, 3 * DM, DM, 0);

    // 4. single-head attention, 4 blocks per batch
    attn_kernel<<<dim3(BB, 4), 256, attn_smem>>>(qkv, att);

    // 5. out-proj + residual -> LN1
    gemm_tc<<<dim3(33, 4), 256>>>(att, attn_out_w, attn_out_b, x0, y, ROWS, DM, DM, 0);
    ln_kernel<<<(ROWS + 7) / 8, 256>>>(y, ln1_g, ln1_b, x1, ROWS);

    // 6. FFN: relu(x@lin1^T) @ lin2^T + residual -> LN2
    gemm_tc<<<dim3(33, 4), 256>>>(x1, lin1_w, lin1_b, nullptr, f, ROWS, DM, DM, 1);
    gemm_tc<<<dim3(33, 4), 256>>>(f, lin2_w, lin2_b, x1, y, ROWS, DM, DM, 0);
    ln_kernel<<<(ROWS + 7) / 8, 256>>>(y, ln2_g, ln2_b, x2, ROWS);

    // 7. classifier head
    head_kernel<<<BB, 256>>>(x2, fc_w, fc_b, out);
}

// round 5
// speedup vs baseline: 1.6477x; 1.1688x over previous
#include <cuda_runtime.h>
#include <math.h>
#include <stdint.h>

#define BB 128
#define LL 512
#define DD 768
#define JJ 32
#define SS 33      // J+1 segments
#define DM 200
#define DF 200
#define ROWS (BB*SS)   // 4224
#define CHUNK 16

// ---------------- scratch (no allocations allowed) ----------------
__device__ float g_pooled[ROWS * DD];   // [B*S, 768]
__device__ float g_x0[ROWS * DM];       // fc1 output
__device__ float g_qkv[ROWS * 3 * DM];  // qkv
__device__ float g_att[ROWS * DM];      // attention output (pre out-proj)
__device__ float g_y[ROWS * DM];        // pre-LN buffer
__device__ float g_x1[ROWS * DM];       // post-LN1
__device__ float g_f[ROWS * DM];        // ffn hidden
__device__ float g_x2[ROWS * DM];       // post-LN2

// =====================================================================
// Kernel 1: fused fc5 scores + per-segment softmax + weighted pooling.
// One block per (b, s). Reads hidden_state exactly once. float4 paths.
// CHUNK=16 -> 52 KB smem -> 4 blocks/SM residency.
// =====================================================================
__global__ void pool_kernel(const float* __restrict__ hidden,
                            const int* __restrict__ cidx,
                            const float* __restrict__ fc5_w,
                            const float* __restrict__ fc5_b,
                            float* __restrict__ pooled) {
    extern __shared__ float sm[];
    float* s_w      = sm;                       // [768]
    float* s_rows   = sm + DD;                  // [CHUNK][768]
    float* s_scores = s_rows + CHUNK * DD;      // [CHUNK]

    int blk = blockIdx.x;
    int b = blk / SS, s = blk % SS;
    int t0 = (s == 0)  ? 0  : cidx[b * JJ + s - 1];
    int t1 = (s == JJ) ? LL : cidx[b * JJ + s];

    int tid = threadIdx.x;
    int lane = tid & 31, wid = tid >> 5;

    for (int i = tid; i < DD / 4; i += 256)
        ((float4*)s_w)[i] = ((const float4*)fc5_w)[i];
    __syncthreads();

    const int d0 = tid, d1 = tid + 256, d2 = tid + 512;
    float acc0 = 0.f, acc1 = 0.f, acc2 = 0.f;
    float m = -INFINITY, l = 0.f;

    for (int c0 = t0; c0 < t1; c0 += CHUNK) {
        int nt = min(CHUNK, t1 - c0);
        for (int tok = wid; tok < nt; tok += 8) {
            const float4* row4 = (const float4*)(hidden + ((long)b * LL + (c0 + tok)) * DD);
            float4* dst4 = (float4*)(s_rows + tok * DD);
            const float4* w4 = (const float4*)s_w;
            float pd = 0.f;
            #pragma unroll
            for (int j = 0; j < 6; j++) {
                int q = lane + 32 * j;
                float4 v = row4[q];
                dst4[q] = v;
                float4 w = w4[q];
                pd += v.x * w.x + v.y * w.y + v.z * w.z + v.w * w.w;
            }
            #pragma unroll
            for (int o = 16; o > 0; o >>= 1)
                pd += __shfl_xor_sync(0xffffffffu, pd, o);
            if (lane == 0) s_scores[tok] = pd + fc5_b[0];
        }
        __syncthreads();

        float cm = -INFINITY;
        for (int t = 0; t < nt; t++) cm = fmaxf(cm, s_scores[t]);
        float nm = fmaxf(m, cm);
        float sc = (m == -INFINITY) ? 0.f : __expf(m - nm);
        acc0 *= sc; acc1 *= sc; acc2 *= sc; l *= sc;
        for (int t = 0; t < nt; t++) {
            float p = __expf(s_scores[t] - nm);
            l += p;
            acc0 += p * s_rows[t * DD + d0];
            acc1 += p * s_rows[t * DD + d1];
            acc2 += p * s_rows[t * DD + d2];
        }
        m = nm;
        __syncthreads();
    }

    float inv = 1.f / l;
    float* out = pooled + (long)blk * DD;
    out[d0] = acc0 * inv;
    out[d1] = acc1 * inv;
    out[d2] = acc2 * inv;
}

// =====================================================================
// Tensor-core GEMM (3xTF32): cp.async double-buffered pipeline.
// C[M,N] = A[M,K] @ W[N,K]^T (+bias)(+res)(relu?)
// Block tile 128x64, 8 warps (4m x 2n), warp tile 32x32, k-step 16.
// =====================================================================
#define KT 16
#define PAF 20                    // row pitch in floats
#define A_BUF (128 * PAF)
#define B_BUF (64 * PAF)

__device__ __forceinline__ void cp_async16(float* smem_dst, const float* gsrc, int src_bytes) {
    uint32_t s = (uint32_t)__cvta_generic_to_shared(smem_dst);
    asm volatile("cp.async.cg.shared.global [%0], [%1], 16, %2;"
                 :: "r"(s), "l"(gsrc), "r"(src_bytes));
}
__device__ __forceinline__ void cp_commit() {
    asm volatile("cp.async.commit_group;");
}
template <int N>
__device__ __forceinline__ void cp_wait() {
    asm volatile("cp.async.wait_group %0;" :: "n"(N));
}

__device__ __forceinline__ float2 split_tf32(float x) {
    uint32_t hu;
    asm("cvt.rna.tf32.f32 %0, %1;" : "=r"(hu) : "f"(x));
    float hi = __uint_as_float(hu);
    uint32_t lu;
    asm("cvt.rna.tf32.f32 %0, %1;" : "=r"(lu) : "f"(x - hi));
    return make_float2(hi, __uint_as_float(lu));
}

__device__ __forceinline__ void mma_tf32(float* c,
                                         uint32_t a0, uint32_t a1, uint32_t a2, uint32_t a3,
                                         uint32_t b0, uint32_t b1) {
    asm volatile(
        "mma.sync.aligned.m16n8k8.row.col.f32.tf32.tf32.f32 "
        "{%0,%1,%2,%3}, {%4,%5,%6,%7}, {%8,%9}, {%0,%1,%2,%3};"
        : "+f"(c[0]), "+f"(c[1]), "+f"(c[2]), "+f"(c[3])
        : "r"(a0), "r"(a1), "r"(a2), "r"(a3), "r"(b0), "r"(b1));
}

__global__ __launch_bounds__(256) void gemm_tc(
        const float* __restrict__ A,
        const float* __restrict__ W,
        const float* __restrict__ bias,
        const float* __restrict__ res,
        float* __restrict__ C,
        int M, int N, int K, int relu) {
    __shared__ float As[2 * A_BUF];
    __shared__ float Bs[2 * B_BUF];

    int tid  = threadIdx.x;
    int lane = tid & 31;
    int wrp  = tid >> 5;
    int wm   = wrp & 3;
    int wn   = wrp >> 2;
    int m0   = blockIdx.x * 128;
    int n0   = blockIdx.y * 64;

    int g = lane >> 2;
    int t = lane & 3;

    float acc[2][4][4];
    #pragma unroll
    for (int mi = 0; mi < 2; mi++)
        #pragma unroll
        for (int ni = 0; ni < 4; ni++)
            #pragma unroll
            for (int r = 0; r < 4; r++) acc[mi][ni][r] = 0.f;

    int lr = tid >> 2;
    int lk = (tid & 3) * 4;

    int NK = (K + KT - 1) / KT;

    auto stage = [&](int kt, int buf) {
        int k0 = kt * KT;
        int kb = (K - (k0 + lk)) * 4;
        int sb = kb < 0 ? 0 : (kb > 16 ? 16 : kb);
        int ko = k0 + lk;
        if (ko > K - 4) ko = (K - 4 < 0) ? 0 : K - 4;
        float* abuf = As + buf * A_BUF;
        float* bbuf = Bs + buf * B_BUF;
        cp_async16(abuf + lr * PAF + lk,        A + (long)(m0 + lr) * K + ko,      sb);
        cp_async16(abuf + (lr + 64) * PAF + lk, A + (long)(m0 + lr + 64) * K + ko, sb);
        int gn = n0 + lr;
        int wb = (gn < N) ? sb : 0;
        int gnc = (gn < N) ? gn : N - 1;
        cp_async16(bbuf + lr * PAF + lk, W + (long)gnc * K + ko, wb);
    };

    stage(0, 0);
    cp_commit();

    for (int kt = 0; kt < NK; kt++) {
        if (kt + 1 < NK) {
            stage(kt + 1, (kt + 1) & 1);
            cp_commit();
            cp_wait<1>();
        } else {
            cp_wait<0>();
        }
        __syncthreads();

        const float* abuf = As + (kt & 1) * A_BUF;
        const float* bbuf = Bs + (kt & 1) * B_BUF;

        #pragma unroll
        for (int ks = 0; ks < KT; ks += 8) {
            float2 ah[2][4];
            #pragma unroll
            for (int mi = 0; mi < 2; mi++) {
                int mb = wm * 32 + mi * 16;
                ah[mi][0] = split_tf32(abuf[(mb + g)     * PAF + ks + t]);
                ah[mi][1] = split_tf32(abuf[(mb + g + 8) * PAF + ks + t]);
                ah[mi][2] = split_tf32(abuf[(mb + g)     * PAF + ks + 4 + t]);
                ah[mi][3] = split_tf32(abuf[(mb + g + 8) * PAF + ks + 4 + t]);
            }
            float2 bh[4][2];
            #pragma unroll
            for (int ni = 0; ni < 4; ni++) {
                int nb = wn * 32 + ni * 8;
                bh[ni][0] = split_tf32(bbuf[(nb + g) * PAF + ks + t]);
                bh[ni][1] = split_tf32(bbuf[(nb + g) * PAF + ks + 4 + t]);
            }
            #pragma unroll
            for (int mi = 0; mi < 2; mi++) {
                uint32_t a0h = __float_as_uint(ah[mi][0].x);
                uint32_t a1h = __float_as_uint(ah[mi][1].x);
                uint32_t a2h = __float_as_uint(ah[mi][2].x);
                uint32_t a3h = __float_as_uint(ah[mi][3].x);
                uint32_t a0l = __float_as_uint(ah[mi][0].y);
                uint32_t a1l = __float_as_uint(ah[mi][1].y);
                uint32_t a2l = __float_as_uint(ah[mi][2].y);
                uint32_t a3l = __float_as_uint(ah[mi][3].y);
                #pragma unroll
                for (int ni = 0; ni < 4; ni++) {
                    uint32_t b0h = __float_as_uint(bh[ni][0].x);
                    uint32_t b1h = __float_as_uint(bh[ni][1].x);
                    uint32_t b0l = __float_as_uint(bh[ni][0].y);
                    uint32_t b1l = __float_as_uint(bh[ni][1].y);
                    float* c = acc[mi][ni];
                    mma_tf32(c, a0h, a1h, a2h, a3h, b0h, b1h);
                    mma_tf32(c, a0h, a1h, a2h, a3h, b0l, b1l);
                    mma_tf32(c, a0l, a1l, a2l, a3l, b0h, b1h);
                }
            }
        }
        __syncthreads();
    }

    #pragma unroll
    for (int mi = 0; mi < 2; mi++) {
        int row0 = m0 + wm * 32 + mi * 16 + g;
        int row1 = row0 + 8;
        #pragma unroll
        for (int ni = 0; ni < 4; ni++) {
            int col = n0 + wn * 32 + ni * 8 + 2 * t;
            if (col >= N) continue;
            float* c = acc[mi][ni];
            float2 bv = make_float2(0.f, 0.f);
            if (bias) bv = *(const float2*)(bias + col);
            float2 v0 = make_float2(c[0] + bv.x, c[1] + bv.y);
            float2 v1 = make_float2(c[2] + bv.x, c[3] + bv.y);
            if (res) {
                float2 r0 = *(const float2*)(res + (long)row0 * N + col);
                float2 r1 = *(const float2*)(res + (long)row1 * N + col);
                v0.x += r0.x; v0.y += r0.y;
                v1.x += r1.x; v1.y += r1.y;
            }
            if (relu) {
                v0.x = fmaxf(v0.x, 0.f); v0.y = fmaxf(v0.y, 0.f);
                v1.x = fmaxf(v1.x, 0.f); v1.y = fmaxf(v1.y, 0.f);
            }
            *(float2*)(C + (long)row0 * N + col) = v0;
            *(float2*)(C + (long)row1 * N + col) = v1;
        }
    }
}

// =====================================================================
// attn v3: warp-per-query-pair, flash-style online softmax, no smem,
// no __syncthreads. 17 warps per batch (16x2 queries + 1x1).
// K/V streamed from global (L2-resident), coalesced LDG.32.
// =====================================================================
#define WPB 17                      // warps per batch
__global__ __launch_bounds__(256) void attn_kernel(
        const float* __restrict__ qkv,
        float* __restrict__ att) {
    int wg   = blockIdx.x * 8 + (threadIdx.x >> 5);   // global warp id
    int lane = threadIdx.x & 31;
    int b = wg / WPB, r = wg % WPB;
    if (b >= BB) return;                               // grid exact anyway
    int i0 = 2 * r;
    int i1 = i0 + 1;
    bool has1 = (i1 < SS);

    const float* base = qkv + (long)b * SS * 3 * DM;
    const float scale = 0.0707106781186547524f;       // 1/sqrt(200)

    // d-ownership: d = lane + 32*m, m = 0..6 (m=6 valid only for lane<8)
    float q0[7], q1[7];
    #pragma unroll
    for (int m = 0; m < 7; m++) {
        int d = lane + 32 * m;
        q0[m] = (d < DM) ? base[(long)i0 * 3 * DM + d] : 0.f;
        q1[m] = (has1 && d < DM) ? base[(long)i1 * 3 * DM + d] : 0.f;
    }

    float o0[7], o1[7];
    #pragma unroll
    for (int m = 0; m < 7; m++) { o0[m] = 0.f; o1[m] = 0.f; }
    float mx0 = -INFINITY, l0 = 0.f;
    float mx1 = -INFINITY, l1 = 0.f;

    for (int j0 = 0; j0 < SS; j0 += 8) {
        float s0[8], s1[8];
        // --- scores for chunk (K streamed once, shared by both queries) ---
        #pragma unroll
        for (int jj = 0; jj < 8; jj++) {
            int j = j0 + jj;
            float p0 = 0.f, p1 = 0.f;
            if (j < SS) {
                const float* krow = base + (long)j * 3 * DM + DM;
                #pragma unroll
                for (int m = 0; m < 7; m++) {
                    int d = lane + 32 * m;
                    float kv = (d < DM) ? krow[d] : 0.f;
                    p0 += q0[m] * kv;
                    p1 += q1[m] * kv;
                }
            }
            s0[jj] = p0; s1[jj] = p1;
        }
        // --- butterfly reductions (all lanes end with full dots) ---
        #pragma unroll
        for (int jj = 0; jj < 8; jj++) {
            #pragma unroll
            for (int o = 16; o > 0; o >>= 1) {
                s0[jj] += __shfl_xor_sync(0xffffffffu, s0[jj], o);
                s1[jj] += __shfl_xor_sync(0xffffffffu, s1[jj], o);
            }
            bool valid = (j0 + jj < SS);
            s0[jj] = valid ? s0[jj] * scale : -INFINITY;
            s1[jj] = valid ? s1[jj] * scale : -INFINITY;
        }
        // --- online softmax update ---
        float cm0 = s0[0], cm1 = s1[0];
        #pragma unroll
        for (int jj = 1; jj < 8; jj++) {
            cm0 = fmaxf(cm0, s0[jj]);
            cm1 = fmaxf(cm1, s1[jj]);
        }
        float nm0 = fmaxf(mx0, cm0), nm1 = fmaxf(mx1, cm1);
        float sc0 = __expf(mx0 - nm0), sc1 = __expf(mx1 - nm1);
        l0 *= sc0; l1 *= sc1;
        #pragma unroll
        for (int m = 0; m < 7; m++) { o0[m] *= sc0; o1[m] *= sc1; }
        mx0 = nm0; mx1 = nm1;

        float p0e[8], p1e[8];
        #pragma unroll
        for (int jj = 0; jj < 8; jj++) {
            p0e[jj] = __expf(s0[jj] - nm0);
            p1e[jj] = __expf(s1[jj] - nm1);
            l0 += p0e[jj];
            l1 += p1e[jj];
        }
        // --- PV accumulate (V streamed once, shared) ---
        #pragma unroll
        for (int jj = 0; jj < 8; jj++) {
            int j = j0 + jj;
            if (j >= SS) break;
            const float* vrow = base + (long)j * 3 * DM + 2 * DM;
            #pragma unroll
            for (int m = 0; m < 7; m++) {
                int d = lane + 32 * m;
                float vv = (d < DM) ? vrow[d] : 0.f;
                o0[m] += p0e[jj] * vv;
                o1[m] += p1e[jj] * vv;
            }
        }
    }

    float inv0 = 1.f / l0;
    float inv1 = 1.f / l1;
    float* out0 = att + ((long)b * SS + i0) * DM;
    #pragma unroll
    for (int m = 0; m < 7; m++) {
        int d = lane + 32 * m;
        if (d < DM) {
            out0[d] = o0[m] * inv0;
            if (has1) out0[DM + d] = o1[m] * inv1;   // row i1 = i0+1 contiguous
        }
    }
}

// =====================================================================
// LayerNorm over DM=200, one warp per row
// =====================================================================
__global__ void ln_kernel(const float* __restrict__ x,
                          const float* __restrict__ g,
                          const float* __restrict__ bta,
                          float* __restrict__ y, int M) {
    int row = blockIdx.x * 8 + (threadIdx.x >> 5);
    int lane = threadIdx.x & 31;
    if (row >= M) return;
    const float* xr = x + (long)row * DM;
    float vals[7];
    float s = 0.f;
    #pragma unroll
    for (int i = 0; i < 7; i++) {
        int d = lane + 32 * i;
        vals[i] = (d < DM) ? xr[d] : 0.f;
        s += vals[i];
    }
    #pragma unroll
    for (int o = 16; o > 0; o >>= 1) s += __shfl_xor_sync(0xffffffffu, s, o);
    float mean = s / (float)DM;
    float vs = 0.f;
    #pragma unroll
    for (int i = 0; i < 7; i++) {
        int d = lane + 32 * i;
        if (d < DM) { float tt = vals[i] - mean; vs += tt * tt; }
    }
    #pragma unroll
    for (int o = 16; o > 0; o >>= 1) vs += __shfl_xor_sync(0xffffffffu, vs, o);
    float inv = rsqrtf(vs / (float)DM + 1e-5f);
    float* yr = y + (long)row * DM;
    #pragma unroll
    for (int i = 0; i < 7; i++) {
        int d = lane + 32 * i;
        if (d < DM) yr[d] = (vals[i] - mean) * inv * g[d] + bta[d];
    }
}

// =====================================================================
// Final head: warp-per-output with shuffle reduction
// =====================================================================
__global__ void head_kernel(const float* __restrict__ x,
                            const float* __restrict__ fcw,
                            const float* __restrict__ fcb,
                            float* __restrict__ out) {
    int b = blockIdx.x;
    int lane = threadIdx.x & 31, wid = threadIdx.x >> 5;
    const float* x0 = x + (long)b * SS * DM;
    for (int oid = wid; oid < (SS - 1) * 2; oid += 8) {
        int srow = 1 + (oid >> 1), c = oid & 1;
        const float* xs = x0 + (long)srow * DM;
        const float* w  = fcw + c * (2 * DM);
        float d = 0.f;
        #pragma unroll
        for (int i = 0; i < 7; i++) {
            int k = lane + 32 * i;
            if (k < DM) d += w[k] * x0[k] + w[DM + k] * xs[k];
        }
        #pragma unroll
        for (int o = 16; o > 0; o >>= 1)
            d += __shfl_xor_sync(0xffffffffu, d, o);
        if (lane == 0)
            out[((long)b * (SS - 1) + (srow - 1)) * 2 + c] = d + fcb[c];
    }
}

// =====================================================================
// Launch
// =====================================================================
extern "C" void kernel_launch(void* const* d_in, const int* in_sizes, int n_in,
                              void* d_out, int out_size) {
    const float* hidden     = (const float*)d_in[0];
    const int*   cidx       = (const int*)  d_in[1];
    const float* fc5_w      = (const float*)d_in[2];
    const float* fc5_b      = (const float*)d_in[3];
    const float* fc1_w      = (const float*)d_in[4];
    const float* fc1_b      = (const float*)d_in[5];
    const float* attn_in_w  = (const float*)d_in[6];
    const float* attn_in_b  = (const float*)d_in[7];
    const float* attn_out_w = (const float*)d_in[8];
    const float* attn_out_b = (const float*)d_in[9];
    const float* ln1_g      = (const float*)d_in[10];
    const float* ln1_b      = (const float*)d_in[11];
    const float* lin1_w     = (const float*)d_in[12];
    const float* lin1_b     = (const float*)d_in[13];
    const float* lin2_w     = (const float*)d_in[14];
    const float* lin2_b     = (const float*)d_in[15];
    const float* ln2_g      = (const float*)d_in[16];
    const float* ln2_b      = (const float*)d_in[17];
    const float* fc_w       = (const float*)d_in[18];
    const float* fc_b       = (const float*)d_in[19];
    float* out = (float*)d_out;

    float *pooled, *x0, *qkv, *att, *y, *x1, *f, *x2;
    cudaGetSymbolAddress((void**)&pooled, g_pooled);
    cudaGetSymbolAddress((void**)&x0,  g_x0);
    cudaGetSymbolAddress((void**)&qkv, g_qkv);
    cudaGetSymbolAddress((void**)&att, g_att);
    cudaGetSymbolAddress((void**)&y,   g_y);
    cudaGetSymbolAddress((void**)&x1,  g_x1);
    cudaGetSymbolAddress((void**)&f,   g_f);
    cudaGetSymbolAddress((void**)&x2,  g_x2);

    const int pool_smem = (DD + CHUNK * DD + CHUNK) * (int)sizeof(float);   // ~52.3 KB
    cudaFuncSetAttribute(pool_kernel, cudaFuncAttributeMaxDynamicSharedMemorySize, pool_smem);

    // 1. fused scores + segment softmax + pooling (single pass over 201 MB)
    pool_kernel<<<BB * SS, 256, pool_smem>>>(hidden, cidx, fc5_w, fc5_b, pooled);

    // 2. fc1: [4224,768] @ [768,200]^T  (tensor core, 3xTF32, pipelined)
    gemm_tc<<<dim3(33, 4), 256>>>(pooled, fc1_w, fc1_b, nullptr, x0, ROWS, DM, DD, 0);

    // 3. qkv: [4224,200] @ [200,600]^T
    gemm_tc<<<dim3(33, 10), 256>>>(x0, attn_in_w, attn_in_b, nullptr, qkv, ROWS, 3 * DM, DM, 0);

    // 4. attention: warp-per-query-pair, 17 warps/batch, 272 blocks
    attn_kernel<<<(BB * WPB + 7) / 8, 256>>>(qkv, att);

    // 5. out-proj + residual -> LN1
    gemm_tc<<<dim3(33, 4), 256>>>(att, attn_out_w, attn_out_b, x0, y, ROWS, DM, DM, 0);
    ln_kernel<<<(ROWS + 7) / 8, 256>>>(y, ln1_g, ln1_b, x1, ROWS);

    // 6. FFN: relu(x@lin1^T) @ lin2^T + residual -> LN2
    gemm_tc<<<dim3(33, 4), 256>>>(x1, lin1_w, lin1_b, nullptr, f, ROWS, DM, DM, 1);
    gemm_tc<<<dim3(33, 4), 256>>>(f, lin2_w, lin2_b, x1, y, ROWS, DM, DM, 0);
    ln_kernel<<<(ROWS + 7) / 8, 256>>>(y, ln2_g, ln2_b, x2, ROWS);

    // 7. classifier head
    head_kernel<<<BB, 256>>>(x2, fc_w, fc_b, out);
}

// round 6
// speedup vs baseline: 1.6666x; 1.0115x over previous
#include <cuda_runtime.h>
#include <math.h>
#include <stdint.h>

#define BB 128
#define LL 512
#define DD 768
#define JJ 32
#define SS 33      // J+1 segments
#define DM 200
#define DF 200
#define ROWS (BB*SS)   // 4224
#define CHUNK 16

// ---------------- scratch (no allocations allowed) ----------------
__device__ float g_pooled[ROWS * DD];   // [B*S, 768]
__device__ float g_x0[ROWS * DM];       // fc1 output
__device__ float g_qkv[ROWS * 3 * DM];  // qkv
__device__ float g_att[ROWS * DM];      // attention output (pre out-proj)
__device__ float g_y[ROWS * DM];        // pre-LN buffer
__device__ float g_x1[ROWS * DM];       // post-LN1
__device__ float g_f[ROWS * DM];        // ffn hidden
__device__ float g_x2[ROWS * DM];       // post-LN2

// =====================================================================
// Kernel 1: fused fc5 scores + per-segment softmax + weighted pooling.
// =====================================================================
__global__ void pool_kernel(const float* __restrict__ hidden,
                            const int* __restrict__ cidx,
                            const float* __restrict__ fc5_w,
                            const float* __restrict__ fc5_b,
                            float* __restrict__ pooled) {
    extern __shared__ float sm[];
    float* s_w      = sm;                       // [768]
    float* s_rows   = sm + DD;                  // [CHUNK][768]
    float* s_scores = s_rows + CHUNK * DD;      // [CHUNK]

    int blk = blockIdx.x;
    int b = blk / SS, s = blk % SS;
    int t0 = (s == 0)  ? 0  : cidx[b * JJ + s - 1];
    int t1 = (s == JJ) ? LL : cidx[b * JJ + s];

    int tid = threadIdx.x;
    int lane = tid & 31, wid = tid >> 5;

    for (int i = tid; i < DD / 4; i += 256)
        ((float4*)s_w)[i] = ((const float4*)fc5_w)[i];
    __syncthreads();

    const int d0 = tid, d1 = tid + 256, d2 = tid + 512;
    float acc0 = 0.f, acc1 = 0.f, acc2 = 0.f;
    float m = -INFINITY, l = 0.f;

    for (int c0 = t0; c0 < t1; c0 += CHUNK) {
        int nt = min(CHUNK, t1 - c0);
        for (int tok = wid; tok < nt; tok += 8) {
            const float4* row4 = (const float4*)(hidden + ((long)b * LL + (c0 + tok)) * DD);
            float4* dst4 = (float4*)(s_rows + tok * DD);
            const float4* w4 = (const float4*)s_w;
            float pd = 0.f;
            #pragma unroll
            for (int j = 0; j < 6; j++) {
                int q = lane + 32 * j;
                float4 v = row4[q];
                dst4[q] = v;
                float4 w = w4[q];
                pd += v.x * w.x + v.y * w.y + v.z * w.z + v.w * w.w;
            }
            #pragma unroll
            for (int o = 16; o > 0; o >>= 1)
                pd += __shfl_xor_sync(0xffffffffu, pd, o);
            if (lane == 0) s_scores[tok] = pd + fc5_b[0];
        }
        __syncthreads();

        float cm = -INFINITY;
        for (int t = 0; t < nt; t++) cm = fmaxf(cm, s_scores[t]);
        float nm = fmaxf(m, cm);
        float sc = (m == -INFINITY) ? 0.f : __expf(m - nm);
        acc0 *= sc; acc1 *= sc; acc2 *= sc; l *= sc;
        for (int t = 0; t < nt; t++) {
            float p = __expf(s_scores[t] - nm);
            l += p;
            acc0 += p * s_rows[t * DD + d0];
            acc1 += p * s_rows[t * DD + d1];
            acc2 += p * s_rows[t * DD + d2];
        }
        m = nm;
        __syncthreads();
    }

    float inv = 1.f / l;
    float* out = pooled + (long)blk * DD;
    out[d0] = acc0 * inv;
    out[d1] = acc1 * inv;
    out[d2] = acc2 * inv;
}

// =====================================================================
// Tensor-core GEMM (3xTF32): cp.async double-buffered pipeline.
// Mask-based hi/lo split: hi = x & 0xFFFFE000 (exact tf32), lo = x - hi
// (HW truncates on mma read; residual error ~2^-24 |x|).
// =====================================================================
#define KT 16
#define PAF 20
#define A_BUF (128 * PAF)
#define B_BUF (64 * PAF)

__device__ __forceinline__ void cp_async16(float* smem_dst, const float* gsrc, int src_bytes) {
    uint32_t s = (uint32_t)__cvta_generic_to_shared(smem_dst);
    asm volatile("cp.async.cg.shared.global [%0], [%1], 16, %2;"
                 :: "r"(s), "l"(gsrc), "r"(src_bytes));
}
__device__ __forceinline__ void cp_commit() {
    asm volatile("cp.async.commit_group;");
}
template <int N>
__device__ __forceinline__ void cp_wait() {
    asm volatile("cp.async.wait_group %0;" :: "n"(N));
}

__device__ __forceinline__ void mma_tf32(float* c,
                                         uint32_t a0, uint32_t a1, uint32_t a2, uint32_t a3,
                                         uint32_t b0, uint32_t b1) {
    asm volatile(
        "mma.sync.aligned.m16n8k8.row.col.f32.tf32.tf32.f32 "
        "{%0,%1,%2,%3}, {%4,%5,%6,%7}, {%8,%9}, {%0,%1,%2,%3};"
        : "+f"(c[0]), "+f"(c[1]), "+f"(c[2]), "+f"(c[3])
        : "r"(a0), "r"(a1), "r"(a2), "r"(a3), "r"(b0), "r"(b1));
}

__global__ __launch_bounds__(256) void gemm_tc(
        const float* __restrict__ A,
        const float* __restrict__ W,
        const float* __restrict__ bias,
        const float* __restrict__ res,
        float* __restrict__ C,
        int M, int N, int K, int relu) {
    __shared__ float As[2 * A_BUF];
    __shared__ float Bs[2 * B_BUF];

    int tid  = threadIdx.x;
    int lane = tid & 31;
    int wrp  = tid >> 5;
    int wm   = wrp & 3;
    int wn   = wrp >> 2;
    int m0   = blockIdx.x * 128;
    int n0   = blockIdx.y * 64;

    int g = lane >> 2;
    int t = lane & 3;

    float acc[2][4][4];
    #pragma unroll
    for (int mi = 0; mi < 2; mi++)
        #pragma unroll
        for (int ni = 0; ni < 4; ni++)
            #pragma unroll
            for (int r = 0; r < 4; r++) acc[mi][ni][r] = 0.f;

    int lr = tid >> 2;
    int lk = (tid & 3) * 4;

    int NK = (K + KT - 1) / KT;

    auto stage = [&](int kt, int buf) {
        int k0 = kt * KT;
        int kb = (K - (k0 + lk)) * 4;
        int sb = kb < 0 ? 0 : (kb > 16 ? 16 : kb);
        int ko = k0 + lk;
        if (ko > K - 4) ko = (K - 4 < 0) ? 0 : K - 4;
        float* abuf = As + buf * A_BUF;
        float* bbuf = Bs + buf * B_BUF;
        cp_async16(abuf + lr * PAF + lk,        A + (long)(m0 + lr) * K + ko,      sb);
        cp_async16(abuf + (lr + 64) * PAF + lk, A + (long)(m0 + lr + 64) * K + ko, sb);
        int gn = n0 + lr;
        int wb = (gn < N) ? sb : 0;
        int gnc = (gn < N) ? gn : N - 1;
        cp_async16(bbuf + lr * PAF + lk, W + (long)gnc * K + ko, wb);
    };

    stage(0, 0);
    cp_commit();

    for (int kt = 0; kt < NK; kt++) {
        if (kt + 1 < NK) {
            stage(kt + 1, (kt + 1) & 1);
            cp_commit();
            cp_wait<1>();
        } else {
            cp_wait<0>();
        }
        __syncthreads();

        const float* abuf = As + (kt & 1) * A_BUF;
        const float* bbuf = Bs + (kt & 1) * B_BUF;

        #pragma unroll
        for (int ks = 0; ks < KT; ks += 8) {
            // raw loads
            float ar[2][4];
            #pragma unroll
            for (int mi = 0; mi < 2; mi++) {
                int mb = wm * 32 + mi * 16;
                ar[mi][0] = abuf[(mb + g)     * PAF + ks + t];
                ar[mi][1] = abuf[(mb + g + 8) * PAF + ks + t];
                ar[mi][2] = abuf[(mb + g)     * PAF + ks + 4 + t];
                ar[mi][3] = abuf[(mb + g + 8) * PAF + ks + 4 + t];
            }
            float br[4][2];
            #pragma unroll
            for (int ni = 0; ni < 4; ni++) {
                int nb = wn * 32 + ni * 8;
                br[ni][0] = bbuf[(nb + g) * PAF + ks + t];
                br[ni][1] = bbuf[(nb + g) * PAF + ks + 4 + t];
            }
            // mask split: hi exact-tf32, lo residual (HW truncates)
            uint32_t ahi[2][4], alo[2][4];
            #pragma unroll
            for (int mi = 0; mi < 2; mi++)
                #pragma unroll
                for (int r = 0; r < 4; r++) {
                    uint32_t h = __float_as_uint(ar[mi][r]) & 0xFFFFE000u;
                    ahi[mi][r] = h;
                    alo[mi][r] = __float_as_uint(ar[mi][r] - __uint_as_float(h));
                }
            uint32_t bhi[4][2], blo[4][2];
            #pragma unroll
            for (int ni = 0; ni < 4; ni++)
                #pragma unroll
                for (int r = 0; r < 2; r++) {
                    uint32_t h = __float_as_uint(br[ni][r]) & 0xFFFFE000u;
                    bhi[ni][r] = h;
                    blo[ni][r] = __float_as_uint(br[ni][r] - __uint_as_float(h));
                }
            #pragma unroll
            for (int mi = 0; mi < 2; mi++) {
                #pragma unroll
                for (int ni = 0; ni < 4; ni++) {
                    float* c = acc[mi][ni];
                    mma_tf32(c, ahi[mi][0], ahi[mi][1], ahi[mi][2], ahi[mi][3],
                             bhi[ni][0], bhi[ni][1]);                       // hi*hi
                    mma_tf32(c, ahi[mi][0], ahi[mi][1], ahi[mi][2], ahi[mi][3],
                             blo[ni][0], blo[ni][1]);                       // hi*lo
                    mma_tf32(c, alo[mi][0], alo[mi][1], alo[mi][2], alo[mi][3],
                             bhi[ni][0], bhi[ni][1]);                       // lo*hi
                }
            }
        }
        __syncthreads();
    }

    #pragma unroll
    for (int mi = 0; mi < 2; mi++) {
        int row0 = m0 + wm * 32 + mi * 16 + g;
        int row1 = row0 + 8;
        #pragma unroll
        for (int ni = 0; ni < 4; ni++) {
            int col = n0 + wn * 32 + ni * 8 + 2 * t;
            if (col >= N) continue;
            float* c = acc[mi][ni];
            float2 bv = make_float2(0.f, 0.f);
            if (bias) bv = *(const float2*)(bias + col);
            float2 v0 = make_float2(c[0] + bv.x, c[1] + bv.y);
            float2 v1 = make_float2(c[2] + bv.x, c[3] + bv.y);
            if (res) {
                float2 r0 = *(const float2*)(res + (long)row0 * N + col);
                float2 r1 = *(const float2*)(res + (long)row1 * N + col);
                v0.x += r0.x; v0.y += r0.y;
                v1.x += r1.x; v1.y += r1.y;
            }
            if (relu) {
                v0.x = fmaxf(v0.x, 0.f); v0.y = fmaxf(v0.y, 0.f);
                v1.x = fmaxf(v1.x, 0.f); v1.y = fmaxf(v1.y, 0.f);
            }
            *(float2*)(C + (long)row0 * N + col) = v0;
            *(float2*)(C + (long)row1 * N + col) = v1;
        }
    }
}

// =====================================================================
// attn v4: ONE query per warp (33 warps/batch, 4224 warps, 528 blocks).
// Flash-style online softmax, no smem, no block barriers.
// =====================================================================
#define WPB 33
__global__ __launch_bounds__(256) void attn_kernel(
        const float* __restrict__ qkv,
        float* __restrict__ att) {
    int wg   = blockIdx.x * 8 + (threadIdx.x >> 5);
    int lane = threadIdx.x & 31;
    if (wg >= BB * WPB) return;
    int b = wg / WPB, i = wg % WPB;

    const float* base = qkv + (long)b * SS * 3 * DM;
    const float scale = 0.0707106781186547524f;   // 1/sqrt(200)

    // d-ownership: d = lane + 32*m
    float q[7];
    #pragma unroll
    for (int m = 0; m < 7; m++) {
        int d = lane + 32 * m;
        q[m] = (d < DM) ? base[(long)i * 3 * DM + d] : 0.f;
    }

    float o[7];
    #pragma unroll
    for (int m = 0; m < 7; m++) o[m] = 0.f;
    float mx = -INFINITY, l = 0.f;

    for (int j0 = 0; j0 < SS; j0 += 8) {
        float s[8];
        #pragma unroll
        for (int jj = 0; jj < 8; jj++) {
            int j = j0 + jj;
            float p = 0.f;
            if (j < SS) {
                const float* krow = base + (long)j * 3 * DM + DM;
                #pragma unroll
                for (int m = 0; m < 7; m++) {
                    int d = lane + 32 * m;
                    float kv = (d < DM) ? krow[d] : 0.f;
                    p += q[m] * kv;
                }
            }
            s[jj] = p;
        }
        #pragma unroll
        for (int jj = 0; jj < 8; jj++) {
            #pragma unroll
            for (int oo = 16; oo > 0; oo >>= 1)
                s[jj] += __shfl_xor_sync(0xffffffffu, s[jj], oo);
            s[jj] = (j0 + jj < SS) ? s[jj] * scale : -INFINITY;
        }
        float cm = s[0];
        #pragma unroll
        for (int jj = 1; jj < 8; jj++) cm = fmaxf(cm, s[jj]);
        float nm = fmaxf(mx, cm);
        float sc = __expf(mx - nm);
        l *= sc;
        #pragma unroll
        for (int m = 0; m < 7; m++) o[m] *= sc;
        mx = nm;

        float pe[8];
        #pragma unroll
        for (int jj = 0; jj < 8; jj++) {
            pe[jj] = __expf(s[jj] - nm);
            l += pe[jj];
        }
        #pragma unroll
        for (int jj = 0; jj < 8; jj++) {
            int j = j0 + jj;
            if (j >= SS) break;
            const float* vrow = base + (long)j * 3 * DM + 2 * DM;
            #pragma unroll
            for (int m = 0; m < 7; m++) {
                int d = lane + 32 * m;
                float vv = (d < DM) ? vrow[d] : 0.f;
                o[m] += pe[jj] * vv;
            }
        }
    }

    float inv = 1.f / l;
    float* outr = att + ((long)b * SS + i) * DM;
    #pragma unroll
    for (int m = 0; m < 7; m++) {
        int d = lane + 32 * m;
        if (d < DM) outr[d] = o[m] * inv;
    }
}

// =====================================================================
// LayerNorm over DM=200, one warp per row
// =====================================================================
__global__ void ln_kernel(const float* __restrict__ x,
                          const float* __restrict__ g,
                          const float* __restrict__ bta,
                          float* __restrict__ y, int M) {
    int row = blockIdx.x * 8 + (threadIdx.x >> 5);
    int lane = threadIdx.x & 31;
    if (row >= M) return;
    const float* xr = x + (long)row * DM;
    float vals[7];
    float s = 0.f;
    #pragma unroll
    for (int i = 0; i < 7; i++) {
        int d = lane + 32 * i;
        vals[i] = (d < DM) ? xr[d] : 0.f;
        s += vals[i];
    }
    #pragma unroll
    for (int o = 16; o > 0; o >>= 1) s += __shfl_xor_sync(0xffffffffu, s, o);
    float mean = s / (float)DM;
    float vs = 0.f;
    #pragma unroll
    for (int i = 0; i < 7; i++) {
        int d = lane + 32 * i;
        if (d < DM) { float tt = vals[i] - mean; vs += tt * tt; }
    }
    #pragma unroll
    for (int o = 16; o > 0; o >>= 1) vs += __shfl_xor_sync(0xffffffffu, vs, o);
    float inv = rsqrtf(vs / (float)DM + 1e-5f);
    float* yr = y + (long)row * DM;
    #pragma unroll
    for (int i = 0; i < 7; i++) {
        int d = lane + 32 * i;
        if (d < DM) yr[d] = (vals[i] - mean) * inv * g[d] + bta[d];
    }
}

// =====================================================================
// Final head: warp-per-output with shuffle reduction
// =====================================================================
__global__ void head_kernel(const float* __restrict__ x,
                            const float* __restrict__ fcw,
                            const float* __restrict__ fcb,
                            float* __restrict__ out) {
    int b = blockIdx.x;
    int lane = threadIdx.x & 31, wid = threadIdx.x >> 5;
    const float* x0 = x + (long)b * SS * DM;
    for (int oid = wid; oid < (SS - 1) * 2; oid += 8) {
        int srow = 1 + (oid >> 1), c = oid & 1;
        const float* xs = x0 + (long)srow * DM;
        const float* w  = fcw + c * (2 * DM);
        float d = 0.f;
        #pragma unroll
        for (int i = 0; i < 7; i++) {
            int k = lane + 32 * i;
            if (k < DM) d += w[k] * x0[k] + w[DM + k] * xs[k];
        }
        #pragma unroll
        for (int o = 16; o > 0; o >>= 1)
            d += __shfl_xor_sync(0xffffffffu, d, o);
        if (lane == 0)
            out[((long)b * (SS - 1) + (srow - 1)) * 2 + c] = d + fcb[c];
    }
}

// =====================================================================
// Launch
// =====================================================================
extern "C" void kernel_launch(void* const* d_in, const int* in_sizes, int n_in,
                              void* d_out, int out_size) {
    const float* hidden     = (const float*)d_in[0];
    const int*   cidx       = (const int*)  d_in[1];
    const float* fc5_w      = (const float*)d_in[2];
    const float* fc5_b      = (const float*)d_in[3];
    const float* fc1_w      = (const float*)d_in[4];
    const float* fc1_b      = (const float*)d_in[5];
    const float* attn_in_w  = (const float*)d_in[6];
    const float* attn_in_b  = (const float*)d_in[7];
    const float* attn_out_w = (const float*)d_in[8];
    const float* attn_out_b = (const float*)d_in[9];
    const float* ln1_g      = (const float*)d_in[10];
    const float* ln1_b      = (const float*)d_in[11];
    const float* lin1_w     = (const float*)d_in[12];
    const float* lin1_b     = (const float*)d_in[13];
    const float* lin2_w     = (const float*)d_in[14];
    const float* lin2_b     = (const float*)d_in[15];
    const float* ln2_g      = (const float*)d_in[16];
    const float* ln2_b      = (const float*)d_in[17];
    const float* fc_w       = (const float*)d_in[18];
    const float* fc_b       = (const float*)d_in[19];
    float* out = (float*)d_out;

    float *pooled, *x0, *qkv, *att, *y, *x1, *f, *x2;
    cudaGetSymbolAddress((void**)&pooled, g_pooled);
    cudaGetSymbolAddress((void**)&x0,  g_x0);
    cudaGetSymbolAddress((void**)&qkv, g_qkv);
    cudaGetSymbolAddress((void**)&att, g_att);
    cudaGetSymbolAddress((void**)&y,   g_y);
    cudaGetSymbolAddress((void**)&x1,  g_x1);
    cudaGetSymbolAddress((void**)&f,   g_f);
    cudaGetSymbolAddress((void**)&x2,  g_x2);

    const int pool_smem = (DD + CHUNK * DD + CHUNK) * (int)sizeof(float);   // ~52.3 KB
    cudaFuncSetAttribute(pool_kernel, cudaFuncAttributeMaxDynamicSharedMemorySize, pool_smem);

    // 1. fused scores + segment softmax + pooling (single pass over 201 MB)
    pool_kernel<<<BB * SS, 256, pool_smem>>>(hidden, cidx, fc5_w, fc5_b, pooled);

    // 2. fc1: [4224,768] @ [768,200]^T  (tensor core, 3xTF32, pipelined)
    gemm_tc<<<dim3(33, 4), 256>>>(pooled, fc1_w, fc1_b, nullptr, x0, ROWS, DM, DD, 0);

    // 3. qkv: [4224,200] @ [200,600]^T
    gemm_tc<<<dim3(33, 10), 256>>>(x0, attn_in_w, attn_in_b, nullptr, qkv, ROWS, 3 * DM, DM, 0);

    // 4. attention: one query per warp, 4224 warps, 528 blocks
    attn_kernel<<<(BB * WPB + 7) / 8, 256>>>(qkv, att);

    // 5. out-proj + residual -> LN1
    gemm_tc<<<dim3(33, 4), 256>>>(att, attn_out_w, attn_out_b, x0, y, ROWS, DM, DM, 0);
    ln_kernel<<<(ROWS + 7) / 8, 256>>>(y, ln1_g, ln1_b, x1, ROWS);

    // 6. FFN: relu(x@lin1^T) @ lin2^T + residual -> LN2
    gemm_tc<<<dim3(33, 4), 256>>>(x1, lin1_w, lin1_b, nullptr, f, ROWS, DM, DM, 1);
    gemm_tc<<<dim3(33, 4), 256>>>(f, lin2_w, lin2_b, x1, y, ROWS, DM, DM, 0);
    ln_kernel<<<(ROWS + 7) / 8, 256>>>(y, ln2_g, ln2_b, x2, ROWS);

    // 7. classifier head
    head_kernel<<<BB, 256>>>(x2, fc_w, fc_b, out);
}